// round 1
// baseline (speedup 1.0000x reference)
#include <cuda_runtime.h>
#include <math.h>

#define B_  2
#define T_  2048
#define C_  2048
#define H_  16
#define HD_ 128
#define C3_ 6144
#define M_  (B_*T_)

// ---------------- scratch (no allocations allowed) ----------------
__device__ float g_qkv[(size_t)B_ * T_ * C3_];   // [B,T,3C]
__device__ float g_att[(size_t)B_ * T_ * C_];    // attention out in [B,T,C]
__device__ float g_cos[T_ * 64];
__device__ float g_sin[T_ * 64];

// ---------------- RoPE tables ----------------
// theta[p] = 10000^(-(2^p)/128), pos is 1-indexed. Computed in double for accuracy.
__global__ void rope_tables_k() {
    int idx = blockIdx.x * blockDim.x + threadIdx.x;
    if (idx >= T_ * 64) return;
    int t = idx >> 6, p = idx & 63;
    double theta = exp(-log(10000.0) * exp2((double)p) / 128.0);
    double ang = (double)(t + 1) * theta;
    g_cos[idx] = (float)cos(ang);
    g_sin[idx] = (float)sin(ang);
}

// ---------------- RoPE apply (in-place on q and k sections of g_qkv) ----------------
// out[d]    = x[d]*cos - x[d+64]*sin      (d < 64)
// out[d+64] = x[d+64]*cos + x[d]*sin      (same cos/sin: theta index d%64)
__global__ void rope_apply_k() {
    int idx = blockIdx.x * blockDim.x + threadIdx.x;  // B*T*H*64 threads
    int d = idx & 63;
    int h = (idx >> 6) & (H_ - 1);
    int t = (idx >> 10) & (T_ - 1);
    int b = idx >> 21;
    float c = g_cos[(t << 6) + d];
    float s = g_sin[(t << 6) + d];
    size_t base = ((size_t)(b * T_ + t)) * C3_ + h * HD_ + d;
#pragma unroll
    for (int sec = 0; sec < 2; sec++) {         // q section (0), k section (+C_)
        float* p = g_qkv + base + sec * C_;
        float x1 = p[0], x2 = p[64];
        p[0]  = x1 * c - x2 * s;
        p[64] = x2 * c + x1 * s;
    }
}

// ---------------- SGEMM (NT): C[m][n] = sum_k A[m][k]*B[n][k] + bias[n] ----------------
// 128x128 block tile, BK=16, 256 threads, 8x8 micro-tile.
#define BK 16
__global__ void __launch_bounds__(256, 2)
sgemm_nt_k(const float* __restrict__ A, const float* __restrict__ Bm,
           const float* __restrict__ bias, float* __restrict__ Cm,
           int K, int ldc) {
    __shared__ float As[BK][132];
    __shared__ float Bs[BK][132];
    const int tid = threadIdx.x;
    const int tx = tid & 15, ty = tid >> 4;
    const int m0 = blockIdx.y * 128, n0 = blockIdx.x * 128;
    const int lr = tid >> 2;            // 0..63
    const int lc = (tid & 3) << 2;      // 0,4,8,12

    const float* Ap = A + (size_t)(m0 + lr) * K + lc;
    const float* Bp = Bm + (size_t)(n0 + lr) * K + lc;

    float acc[8][8];
#pragma unroll
    for (int i = 0; i < 8; i++)
#pragma unroll
        for (int j = 0; j < 8; j++) acc[i][j] = 0.f;

    for (int kt = 0; kt < K; kt += BK) {
        float4 a0 = *(const float4*)(Ap + kt);
        float4 a1 = *(const float4*)(Ap + kt + (size_t)64 * K);
        float4 b0 = *(const float4*)(Bp + kt);
        float4 b1 = *(const float4*)(Bp + kt + (size_t)64 * K);
        As[lc + 0][lr] = a0.x; As[lc + 1][lr] = a0.y; As[lc + 2][lr] = a0.z; As[lc + 3][lr] = a0.w;
        As[lc + 0][lr + 64] = a1.x; As[lc + 1][lr + 64] = a1.y; As[lc + 2][lr + 64] = a1.z; As[lc + 3][lr + 64] = a1.w;
        Bs[lc + 0][lr] = b0.x; Bs[lc + 1][lr] = b0.y; Bs[lc + 2][lr] = b0.z; Bs[lc + 3][lr] = b0.w;
        Bs[lc + 0][lr + 64] = b1.x; Bs[lc + 1][lr + 64] = b1.y; Bs[lc + 2][lr + 64] = b1.z; Bs[lc + 3][lr + 64] = b1.w;
        __syncthreads();
#pragma unroll
        for (int kk = 0; kk < BK; kk++) {
            float ar[8], br[8];
            *(float4*)(ar)     = *(float4*)&As[kk][ty * 8];
            *(float4*)(ar + 4) = *(float4*)&As[kk][ty * 8 + 4];
            *(float4*)(br)     = *(float4*)&Bs[kk][tx * 8];
            *(float4*)(br + 4) = *(float4*)&Bs[kk][tx * 8 + 4];
#pragma unroll
            for (int i = 0; i < 8; i++)
#pragma unroll
                for (int j = 0; j < 8; j++) acc[i][j] += ar[i] * br[j];
        }
        __syncthreads();
    }

    float bb[8];
#pragma unroll
    for (int j = 0; j < 8; j++) bb[j] = bias[n0 + tx * 8 + j];
#pragma unroll
    for (int i = 0; i < 8; i++) {
        size_t off = (size_t)(m0 + ty * 8 + i) * ldc + n0 + tx * 8;
        float4 w0 = make_float4(acc[i][0] + bb[0], acc[i][1] + bb[1], acc[i][2] + bb[2], acc[i][3] + bb[3]);
        float4 w1 = make_float4(acc[i][4] + bb[4], acc[i][5] + bb[5], acc[i][6] + bb[6], acc[i][7] + bb[7]);
        *(float4*)(Cm + off)     = w0;
        *(float4*)(Cm + off + 4) = w1;
    }
}

// ---------------- Flash attention (causal, online softmax) ----------------
// Block: (q-tile 64 rows) x (head) x (batch). 256 threads.
// S tile 64x64: thread (ty,tx) owns rows ty*4+i, cols tx+16*j (conflict-free smem).
// O tile 64x128: thread owns rows ty*4+i, cols tx*8..tx*8+7.
#define QS_STRIDE 132
#define PS_STRIDE 68
#define FA_SMEM_FLOATS (3 * 64 * QS_STRIDE + 64 * PS_STRIDE)
#define FA_SMEM_BYTES  (FA_SMEM_FLOATS * 4)

__global__ void __launch_bounds__(256)
flash_attn_k() {
    extern __shared__ float sm[];
    float* Qs = sm;
    float* Ks = sm + 64 * QS_STRIDE;
    float* Vs = sm + 2 * 64 * QS_STRIDE;
    float* Ps = sm + 3 * 64 * QS_STRIDE;

    const int tid = threadIdx.x;
    const int tx = tid & 15, ty = tid >> 4;
    const int qb = blockIdx.x, h = blockIdx.y, b = blockIdx.z;
    const int q0 = qb * 64;
    const float scale = 0.08838834764831845f;  // 1/sqrt(128)

    const float* qbase = g_qkv + (size_t)(b * T_ + q0) * C3_ + h * HD_;
    for (int i = tid; i < 64 * 32; i += 256) {
        int r = i >> 5, c4 = (i & 31) << 2;
        *(float4*)&Qs[r * QS_STRIDE + c4] = *(const float4*)(qbase + (size_t)r * C3_ + c4);
    }

    float m_[4], l_[4], o_[4][8];
#pragma unroll
    for (int i = 0; i < 4; i++) {
        m_[i] = -1e30f; l_[i] = 0.f;
#pragma unroll
        for (int cc = 0; cc < 8; cc++) o_[i][cc] = 0.f;
    }

    for (int kt = 0; kt <= qb; kt++) {
        const float* kbase = g_qkv + (size_t)(b * T_ + kt * 64) * C3_ + C_ + h * HD_;
        const float* vbase = kbase + C_;
        for (int i = tid; i < 64 * 32; i += 256) {
            int r = i >> 5, c4 = (i & 31) << 2;
            *(float4*)&Ks[r * QS_STRIDE + c4] = *(const float4*)(kbase + (size_t)r * C3_ + c4);
            *(float4*)&Vs[r * QS_STRIDE + c4] = *(const float4*)(vbase + (size_t)r * C3_ + c4);
        }
        __syncthreads();

        // S = Q K^T
        float s[4][4];
#pragma unroll
        for (int i = 0; i < 4; i++)
#pragma unroll
            for (int j = 0; j < 4; j++) s[i][j] = 0.f;

#pragma unroll 2
        for (int d = 0; d < HD_; d += 4) {
            float4 qv[4], kv[4];
#pragma unroll
            for (int i = 0; i < 4; i++) qv[i] = *(float4*)&Qs[(ty * 4 + i) * QS_STRIDE + d];
#pragma unroll
            for (int j = 0; j < 4; j++) kv[j] = *(float4*)&Ks[(tx + 16 * j) * QS_STRIDE + d];
#pragma unroll
            for (int i = 0; i < 4; i++)
#pragma unroll
                for (int j = 0; j < 4; j++)
                    s[i][j] += qv[i].x * kv[j].x + qv[i].y * kv[j].y +
                               qv[i].z * kv[j].z + qv[i].w * kv[j].w;
        }

        const bool diag = (kt == qb);
#pragma unroll
        for (int i = 0; i < 4; i++) {
            int qg = q0 + ty * 4 + i;
            float mx = -1e30f;
#pragma unroll
            for (int j = 0; j < 4; j++) {
                float v = s[i][j] * scale;
                if (diag && (kt * 64 + tx + 16 * j) > qg) v = -1e30f;
                s[i][j] = v;
                mx = fmaxf(mx, v);
            }
#pragma unroll
            for (int off = 1; off < 16; off <<= 1)
                mx = fmaxf(mx, __shfl_xor_sync(0xffffffffu, mx, off));
            float mn = fmaxf(m_[i], mx);
            float al = __expf(m_[i] - mn);
            m_[i] = mn;
            float rs = 0.f;
#pragma unroll
            for (int j = 0; j < 4; j++) {
                float p = __expf(s[i][j] - mn);
                Ps[(ty * 4 + i) * PS_STRIDE + tx + 16 * j] = p;
                rs += p;
            }
#pragma unroll
            for (int off = 1; off < 16; off <<= 1)
                rs += __shfl_xor_sync(0xffffffffu, rs, off);
            l_[i] = l_[i] * al + rs;
#pragma unroll
            for (int cc = 0; cc < 8; cc++) o_[i][cc] *= al;
        }
        __syncthreads();

        // O += P @ V
#pragma unroll 2
        for (int k = 0; k < 64; k += 4) {
            float4 pv[4];
#pragma unroll
            for (int i = 0; i < 4; i++) pv[i] = *(float4*)&Ps[(ty * 4 + i) * PS_STRIDE + k];
#pragma unroll
            for (int kk = 0; kk < 4; kk++) {
                float4 v0 = *(float4*)&Vs[(k + kk) * QS_STRIDE + tx * 8];
                float4 v1 = *(float4*)&Vs[(k + kk) * QS_STRIDE + tx * 8 + 4];
#pragma unroll
                for (int i = 0; i < 4; i++) {
                    float p = (kk == 0) ? pv[i].x : (kk == 1) ? pv[i].y : (kk == 2) ? pv[i].z : pv[i].w;
                    o_[i][0] += p * v0.x; o_[i][1] += p * v0.y;
                    o_[i][2] += p * v0.z; o_[i][3] += p * v0.w;
                    o_[i][4] += p * v1.x; o_[i][5] += p * v1.y;
                    o_[i][6] += p * v1.z; o_[i][7] += p * v1.w;
                }
            }
        }
        __syncthreads();
    }

    // normalize + write to g_att in [B,T,C] layout (transpose-back is free)
    float* obase = g_att + (size_t)(b * T_ + q0) * C_ + h * HD_;
#pragma unroll
    for (int i = 0; i < 4; i++) {
        float inv = 1.f / l_[i];
        float4 r0 = make_float4(o_[i][0] * inv, o_[i][1] * inv, o_[i][2] * inv, o_[i][3] * inv);
        float4 r1 = make_float4(o_[i][4] * inv, o_[i][5] * inv, o_[i][6] * inv, o_[i][7] * inv);
        *(float4*)(obase + (size_t)(ty * 4 + i) * C_ + tx * 8)     = r0;
        *(float4*)(obase + (size_t)(ty * 4 + i) * C_ + tx * 8 + 4) = r1;
    }
}

// ---------------- launch ----------------
extern "C" void kernel_launch(void* const* d_in, const int* in_sizes, int n_in,
                              void* d_out, int out_size) {
    const float* x    = (const float*)d_in[0];
    const float* Wqkv = (const float*)d_in[1];
    const float* bqkv = (const float*)d_in[2];
    const float* Wo   = (const float*)d_in[3];
    const float* bo   = (const float*)d_in[4];
    float* out = (float*)d_out;

    void* qkv_p = nullptr; cudaGetSymbolAddress(&qkv_p, g_qkv);
    void* att_p = nullptr; cudaGetSymbolAddress(&att_p, g_att);

    cudaFuncSetAttribute(flash_attn_k, cudaFuncAttributeMaxDynamicSharedMemorySize, FA_SMEM_BYTES);

    // 1. RoPE tables
    rope_tables_k<<<(T_ * 64 + 255) / 256, 256>>>();
    // 2. QKV projection: [4096,2048] x [6144,2048]^T -> [4096,6144]
    sgemm_nt_k<<<dim3(C3_ / 128, M_ / 128), 256>>>(x, Wqkv, bqkv, (float*)qkv_p, C_, C3_);
    // 3. RoPE on q,k
    rope_apply_k<<<(B_ * T_ * H_ * 64) / 256, 256>>>();
    // 4. causal flash attention -> g_att [B,T,C]
    flash_attn_k<<<dim3(T_ / 64, H_, B_), 256, FA_SMEM_BYTES>>>();
    // 5. output projection -> d_out
    sgemm_nt_k<<<dim3(C_ / 128, M_ / 128), 256>>>((const float*)att_p, Wo, bo, out, C_, C_);
}

// round 4
// speedup vs baseline: 1.5725x; 1.5725x over previous
#include <cuda_runtime.h>
#include <cuda_bf16.h>
#include <cstdint>
#include <math.h>

#define B_  2
#define T_  2048
#define C_  2048
#define H_  16
#define HD_ 128
#define C3_ 6144
#define M_  (B_*T_)

// ---------------- scratch (no allocations allowed) ----------------
__device__ float g_qkv[(size_t)B_ * T_ * C3_];   // [B,T,3C]
__device__ float g_att[(size_t)B_ * T_ * C_];    // attention out in [B,T,C]
__device__ float g_cos[T_ * 64];
__device__ float g_sin[T_ * 64];

// ---------------- RoPE tables ----------------
__global__ void rope_tables_k() {
    int idx = blockIdx.x * blockDim.x + threadIdx.x;
    if (idx >= T_ * 64) return;
    int t = idx >> 6, p = idx & 63;
    double theta = exp(-log(10000.0) * exp2((double)p) / 128.0);
    double ang = (double)(t + 1) * theta;
    g_cos[idx] = (float)cos(ang);
    g_sin[idx] = (float)sin(ang);
}

// ---------------- RoPE apply ----------------
__global__ void rope_apply_k() {
    int idx = blockIdx.x * blockDim.x + threadIdx.x;
    int d = idx & 63;
    int h = (idx >> 6) & (H_ - 1);
    int t = (idx >> 10) & (T_ - 1);
    int b = idx >> 21;
    float c = g_cos[(t << 6) + d];
    float s = g_sin[(t << 6) + d];
    size_t base = ((size_t)(b * T_ + t)) * C3_ + h * HD_ + d;
#pragma unroll
    for (int sec = 0; sec < 2; sec++) {
        float* p = g_qkv + base + sec * C_;
        float x1 = p[0], x2 = p[64];
        p[0]  = x1 * c - x2 * s;
        p[64] = x2 * c + x1 * s;
    }
}

// ================= mma.sync helpers =================
__device__ __forceinline__ uint32_t smem_u32(const void* p) {
    uint32_t a;
    asm("{ .reg .u64 t; cvta.to.shared.u64 t, %1; cvt.u32.u64 %0, t; }" : "=r"(a) : "l"(p));
    return a;
}
__device__ __forceinline__ void mma_bf16(float* c, const uint32_t* a, const uint32_t* b) {
    asm volatile(
        "mma.sync.aligned.m16n8k16.row.col.f32.bf16.bf16.f32 "
        "{%0,%1,%2,%3}, {%4,%5,%6,%7}, {%8,%9}, {%0,%1,%2,%3};"
        : "+f"(c[0]), "+f"(c[1]), "+f"(c[2]), "+f"(c[3])
        : "r"(a[0]), "r"(a[1]), "r"(a[2]), "r"(a[3]), "r"(b[0]), "r"(b[1]));
}
__device__ __forceinline__ void ldsm_x4(uint32_t* d, uint32_t addr) {
    asm volatile("ldmatrix.sync.aligned.m8n8.x4.shared.b16 {%0,%1,%2,%3}, [%4];"
                 : "=r"(d[0]), "=r"(d[1]), "=r"(d[2]), "=r"(d[3]) : "r"(addr));
}
__device__ __forceinline__ void ldsm_x2(uint32_t* d, uint32_t addr) {
    asm volatile("ldmatrix.sync.aligned.m8n8.x2.shared.b16 {%0,%1}, [%2];"
                 : "=r"(d[0]), "=r"(d[1]) : "r"(addr));
}
// hi = top-16-bit truncation of fp32 (exactly representable in bf16, residual exact)
__device__ __forceinline__ uint32_t pack_hi(float x0, float x1) {
    uint32_t u0 = __float_as_uint(x0), u1 = __float_as_uint(x1);
    return (u0 >> 16) | (u1 & 0xFFFF0000u);
}
__device__ __forceinline__ uint32_t pack_lo(float x0, float x1) {
    float h0 = __uint_as_float(__float_as_uint(x0) & 0xFFFF0000u);
    float h1 = __uint_as_float(__float_as_uint(x1) & 0xFFFF0000u);
    __nv_bfloat162 v = __floats2bfloat162_rn(x0 - h0, x1 - h1);
    return *reinterpret_cast<uint32_t*>(&v);
}

// ================= bf16x3 HMMA GEMM (NT): C = A[M,K]*B[N,K]^T + bias =================
// 128x128 CTA tile, BK=32, 8 warps (2x4), warp tile 64x32, 2-stage smem pipeline.
// smem rows padded to 40 halfs (80B) -> conflict-free ldmatrix.
#define GBK 32
#define ROWH 40                       // halfs per smem row
#define TILE_H_BYTES (128 * ROWH * 2) // 10240
#define G_STAGE (4 * TILE_H_BYTES)    // Ah, Al, Bh, Bl
#define GEMM_SMEM (2 * G_STAGE)       // 81920

__global__ void __launch_bounds__(256)
gemm_mma_k(const float* __restrict__ A, const float* __restrict__ Bm,
           const float* __restrict__ bias, float* __restrict__ Cm,
           int K, int ldc) {
    extern __shared__ char smem[];
    const uint32_t sb = smem_u32(smem);
    const int tid = threadIdx.x;
    const int wid = tid >> 5, lid = tid & 31;
    const int m0 = blockIdx.y * 128, n0 = blockIdx.x * 128;

    // loader mapping: 2 threads per row, 16 floats each
    const int lr = tid >> 1;
    const int lc0 = (tid & 1) * 16;
    const float* Ap = A + (size_t)(m0 + lr) * K + lc0;
    const float* Bp = Bm + (size_t)(n0 + lr) * K + lc0;
    const uint32_t sts_off = (uint32_t)(lr * ROWH + lc0) * 2;  // bytes within a tile

    // warp tiling
    const int wm = (wid >> 2) * 64, wn = (wid & 3) * 32;
    // ldmatrix lane address components
    const int a_row = (lid & 7) + ((lid >> 3) & 1) * 8;
    const int a_kb  = ((lid >> 4) & 1) * 8;
    const int b_row = lid & 7;
    const int b_kb  = ((lid >> 3) & 1) * 8;

    float acc[4][4][4];
#pragma unroll
    for (int i = 0; i < 4; i++)
#pragma unroll
        for (int j = 0; j < 4; j++)
#pragma unroll
            for (int c = 0; c < 4; c++) acc[i][j][c] = 0.f;

    const int nch = K / GBK;
    float4 la[4], lb[4];

    // prologue: load chunk 0, convert+store to stage 0
#pragma unroll
    for (int j = 0; j < 4; j++) { la[j] = *(const float4*)(Ap + j * 4); lb[j] = *(const float4*)(Bp + j * 4); }
#pragma unroll
    for (int j = 0; j < 4; j++) {
        uint32_t o = sts_off + j * 8;
        *(uint2*)(smem + 0 * TILE_H_BYTES + o) = make_uint2(pack_hi(la[j].x, la[j].y), pack_hi(la[j].z, la[j].w));
        *(uint2*)(smem + 1 * TILE_H_BYTES + o) = make_uint2(pack_lo(la[j].x, la[j].y), pack_lo(la[j].z, la[j].w));
        *(uint2*)(smem + 2 * TILE_H_BYTES + o) = make_uint2(pack_hi(lb[j].x, lb[j].y), pack_hi(lb[j].z, lb[j].w));
        *(uint2*)(smem + 3 * TILE_H_BYTES + o) = make_uint2(pack_lo(lb[j].x, lb[j].y), pack_lo(lb[j].z, lb[j].w));
    }

    for (int ch = 0; ch < nch; ch++) {
        __syncthreads();
        // prefetch next chunk into regs
        if (ch + 1 < nch) {
            const size_t ko = (size_t)(ch + 1) * GBK;
#pragma unroll
            for (int j = 0; j < 4; j++) { la[j] = *(const float4*)(Ap + ko + j * 4); lb[j] = *(const float4*)(Bp + ko + j * 4); }
        }
        // compute on stage s
        const uint32_t st = sb + (uint32_t)(ch & 1) * G_STAGE;
#pragma unroll
        for (int ks = 0; ks < 2; ks++) {
            uint32_t ah[4][4], al[4][4], bh[4][2], bl[4][2];
#pragma unroll
            for (int mt = 0; mt < 4; mt++) {
                uint32_t ro = (uint32_t)((wm + mt * 16 + a_row) * ROWH + ks * 16 + a_kb) * 2;
                ldsm_x4(ah[mt], st + 0 * TILE_H_BYTES + ro);
                ldsm_x4(al[mt], st + 1 * TILE_H_BYTES + ro);
            }
#pragma unroll
            for (int nt = 0; nt < 4; nt++) {
                uint32_t ro = (uint32_t)((wn + nt * 8 + b_row) * ROWH + ks * 16 + b_kb) * 2;
                ldsm_x2(bh[nt], st + 2 * TILE_H_BYTES + ro);
                ldsm_x2(bl[nt], st + 3 * TILE_H_BYTES + ro);
            }
#pragma unroll
            for (int mt = 0; mt < 4; mt++)
#pragma unroll
                for (int nt = 0; nt < 4; nt++) {
                    mma_bf16(acc[mt][nt], ah[mt], bh[nt]);
                    mma_bf16(acc[mt][nt], ah[mt], bl[nt]);
                    mma_bf16(acc[mt][nt], al[mt], bh[nt]);
                }
        }
        // store next chunk to the other stage
        if (ch + 1 < nch) {
            char* dst = smem + ((ch + 1) & 1) * G_STAGE;
#pragma unroll
            for (int j = 0; j < 4; j++) {
                uint32_t o = sts_off + j * 8;
                *(uint2*)(dst + 0 * TILE_H_BYTES + o) = make_uint2(pack_hi(la[j].x, la[j].y), pack_hi(la[j].z, la[j].w));
                *(uint2*)(dst + 1 * TILE_H_BYTES + o) = make_uint2(pack_lo(la[j].x, la[j].y), pack_lo(la[j].z, la[j].w));
                *(uint2*)(dst + 2 * TILE_H_BYTES + o) = make_uint2(pack_hi(lb[j].x, lb[j].y), pack_hi(lb[j].z, lb[j].w));
                *(uint2*)(dst + 3 * TILE_H_BYTES + o) = make_uint2(pack_lo(lb[j].x, lb[j].y), pack_lo(lb[j].z, lb[j].w));
            }
        }
    }

    // epilogue: direct stores with bias
    const int cr = lid >> 2, cc = (lid & 3) * 2;
#pragma unroll
    for (int mt = 0; mt < 4; mt++) {
#pragma unroll
        for (int nt = 0; nt < 4; nt++) {
            int gr = m0 + wm + mt * 16 + cr;
            int gc = n0 + wn + nt * 8 + cc;
            float b0 = bias[gc], b1 = bias[gc + 1];
            float* p0 = Cm + (size_t)gr * ldc + gc;
            float* p1 = Cm + (size_t)(gr + 8) * ldc + gc;
            *(float2*)p0 = make_float2(acc[mt][nt][0] + b0, acc[mt][nt][1] + b1);
            *(float2*)p1 = make_float2(acc[mt][nt][2] + b0, acc[mt][nt][3] + b1);
        }
    }
}

// ---------------- Flash attention (causal, online softmax) ----------------
#define QS_STRIDE 132
#define PS_STRIDE 68
#define FA_SMEM_FLOATS (3 * 64 * QS_STRIDE + 64 * PS_STRIDE)
#define FA_SMEM_BYTES  (FA_SMEM_FLOATS * 4)

__global__ void __launch_bounds__(256)
flash_attn_k() {
    extern __shared__ float sm[];
    float* Qs = sm;
    float* Ks = sm + 64 * QS_STRIDE;
    float* Vs = sm + 2 * 64 * QS_STRIDE;
    float* Ps = sm + 3 * 64 * QS_STRIDE;

    const int tid = threadIdx.x;
    const int tx = tid & 15, ty = tid >> 4;
    const int qb = blockIdx.x, h = blockIdx.y, b = blockIdx.z;
    const int q0 = qb * 64;
    const float scale = 0.08838834764831845f;

    const float* qbase = g_qkv + (size_t)(b * T_ + q0) * C3_ + h * HD_;
    for (int i = tid; i < 64 * 32; i += 256) {
        int r = i >> 5, c4 = (i & 31) << 2;
        *(float4*)&Qs[r * QS_STRIDE + c4] = *(const float4*)(qbase + (size_t)r * C3_ + c4);
    }

    float m_[4], l_[4], o_[4][8];
#pragma unroll
    for (int i = 0; i < 4; i++) {
        m_[i] = -1e30f; l_[i] = 0.f;
#pragma unroll
        for (int cc = 0; cc < 8; cc++) o_[i][cc] = 0.f;
    }

    for (int kt = 0; kt <= qb; kt++) {
        const float* kbase = g_qkv + (size_t)(b * T_ + kt * 64) * C3_ + C_ + h * HD_;
        const float* vbase = kbase + C_;
        for (int i = tid; i < 64 * 32; i += 256) {
            int r = i >> 5, c4 = (i & 31) << 2;
            *(float4*)&Ks[r * QS_STRIDE + c4] = *(const float4*)(kbase + (size_t)r * C3_ + c4);
            *(float4*)&Vs[r * QS_STRIDE + c4] = *(const float4*)(vbase + (size_t)r * C3_ + c4);
        }
        __syncthreads();

        float s[4][4];
#pragma unroll
        for (int i = 0; i < 4; i++)
#pragma unroll
            for (int j = 0; j < 4; j++) s[i][j] = 0.f;

#pragma unroll 2
        for (int d = 0; d < HD_; d += 4) {
            float4 qv[4], kv[4];
#pragma unroll
            for (int i = 0; i < 4; i++) qv[i] = *(float4*)&Qs[(ty * 4 + i) * QS_STRIDE + d];
#pragma unroll
            for (int j = 0; j < 4; j++) kv[j] = *(float4*)&Ks[(tx + 16 * j) * QS_STRIDE + d];
#pragma unroll
            for (int i = 0; i < 4; i++)
#pragma unroll
                for (int j = 0; j < 4; j++)
                    s[i][j] += qv[i].x * kv[j].x + qv[i].y * kv[j].y +
                               qv[i].z * kv[j].z + qv[i].w * kv[j].w;
        }

        const bool diag = (kt == qb);
#pragma unroll
        for (int i = 0; i < 4; i++) {
            int qg = q0 + ty * 4 + i;
            float mx = -1e30f;
#pragma unroll
            for (int j = 0; j < 4; j++) {
                float v = s[i][j] * scale;
                if (diag && (kt * 64 + tx + 16 * j) > qg) v = -1e30f;
                s[i][j] = v;
                mx = fmaxf(mx, v);
            }
#pragma unroll
            for (int off = 1; off < 16; off <<= 1)
                mx = fmaxf(mx, __shfl_xor_sync(0xffffffffu, mx, off));
            float mn = fmaxf(m_[i], mx);
            float al = __expf(m_[i] - mn);
            m_[i] = mn;
            float rs = 0.f;
#pragma unroll
            for (int j = 0; j < 4; j++) {
                float p = __expf(s[i][j] - mn);
                Ps[(ty * 4 + i) * PS_STRIDE + tx + 16 * j] = p;
                rs += p;
            }
#pragma unroll
            for (int off = 1; off < 16; off <<= 1)
                rs += __shfl_xor_sync(0xffffffffu, rs, off);
            l_[i] = l_[i] * al + rs;
#pragma unroll
            for (int cc = 0; cc < 8; cc++) o_[i][cc] *= al;
        }
        __syncthreads();

#pragma unroll 2
        for (int k = 0; k < 64; k += 4) {
            float4 pv[4];
#pragma unroll
            for (int i = 0; i < 4; i++) pv[i] = *(float4*)&Ps[(ty * 4 + i) * PS_STRIDE + k];
#pragma unroll
            for (int kk = 0; kk < 4; kk++) {
                float4 v0 = *(float4*)&Vs[(k + kk) * QS_STRIDE + tx * 8];
                float4 v1 = *(float4*)&Vs[(k + kk) * QS_STRIDE + tx * 8 + 4];
#pragma unroll
                for (int i = 0; i < 4; i++) {
                    float p = (kk == 0) ? pv[i].x : (kk == 1) ? pv[i].y : (kk == 2) ? pv[i].z : pv[i].w;
                    o_[i][0] += p * v0.x; o_[i][1] += p * v0.y;
                    o_[i][2] += p * v0.z; o_[i][3] += p * v0.w;
                    o_[i][4] += p * v1.x; o_[i][5] += p * v1.y;
                    o_[i][6] += p * v1.z; o_[i][7] += p * v1.w;
                }
            }
        }
        __syncthreads();
    }

    float* obase = g_att + (size_t)(b * T_ + q0) * C_ + h * HD_;
#pragma unroll
    for (int i = 0; i < 4; i++) {
        float inv = 1.f / l_[i];
        float4 r0 = make_float4(o_[i][0] * inv, o_[i][1] * inv, o_[i][2] * inv, o_[i][3] * inv);
        float4 r1 = make_float4(o_[i][4] * inv, o_[i][5] * inv, o_[i][6] * inv, o_[i][7] * inv);
        *(float4*)(obase + (size_t)(ty * 4 + i) * C_ + tx * 8)     = r0;
        *(float4*)(obase + (size_t)(ty * 4 + i) * C_ + tx * 8 + 4) = r1;
    }
}

// ---------------- launch ----------------
extern "C" void kernel_launch(void* const* d_in, const int* in_sizes, int n_in,
                              void* d_out, int out_size) {
    const float* x    = (const float*)d_in[0];
    const float* Wqkv = (const float*)d_in[1];
    const float* bqkv = (const float*)d_in[2];
    const float* Wo   = (const float*)d_in[3];
    const float* bo   = (const float*)d_in[4];
    float* out = (float*)d_out;

    void* qkv_p = nullptr; cudaGetSymbolAddress(&qkv_p, g_qkv);
    void* att_p = nullptr; cudaGetSymbolAddress(&att_p, g_att);

    cudaFuncSetAttribute(flash_attn_k, cudaFuncAttributeMaxDynamicSharedMemorySize, FA_SMEM_BYTES);
    cudaFuncSetAttribute(gemm_mma_k, cudaFuncAttributeMaxDynamicSharedMemorySize, GEMM_SMEM);

    // 1. RoPE tables
    rope_tables_k<<<(T_ * 64 + 255) / 256, 256>>>();
    // 2. QKV projection (HMMA bf16x3): [4096,2048] x [6144,2048]^T -> [4096,6144]
    gemm_mma_k<<<dim3(C3_ / 128, M_ / 128), 256, GEMM_SMEM>>>(x, Wqkv, bqkv, (float*)qkv_p, C_, C3_);
    // 3. RoPE on q,k
    rope_apply_k<<<(B_ * T_ * H_ * 64) / 256, 256>>>();
    // 4. causal flash attention -> g_att [B,T,C]
    flash_attn_k<<<dim3(T_ / 64, H_, B_), 256, FA_SMEM_BYTES>>>();
    // 5. output projection (HMMA bf16x3) -> d_out
    gemm_mma_k<<<dim3(C_ / 128, M_ / 128), 256, GEMM_SMEM>>>((const float*)att_p, Wo, bo, out, C_, C_);
}

// round 5
// speedup vs baseline: 2.3371x; 1.4862x over previous
#include <cuda_runtime.h>
#include <cuda_bf16.h>
#include <cstdint>
#include <math.h>

#define B_  2
#define T_  2048
#define C_  2048
#define H_  16
#define HD_ 128
#define C3_ 6144
#define M_  (B_*T_)

// ---------------- scratch (no allocations allowed) ----------------
__device__ float g_qkv[(size_t)B_ * T_ * C3_];   // [B,T,3C] (q,k un-roped; rope fused in attn)
__device__ float g_att[(size_t)B_ * T_ * C_];    // attention out in [B,T,C]
__device__ float g_cos[T_ * 64];
__device__ float g_sin[T_ * 64];

// ---------------- RoPE tables ----------------
__global__ void rope_tables_k() {
    int idx = blockIdx.x * blockDim.x + threadIdx.x;
    if (idx >= T_ * 64) return;
    int t = idx >> 6, p = idx & 63;
    double theta = exp(-log(10000.0) * exp2((double)p) / 128.0);
    double ang = (double)(t + 1) * theta;
    g_cos[idx] = (float)cos(ang);
    g_sin[idx] = (float)sin(ang);
}

// ================= mma.sync helpers =================
__device__ __forceinline__ uint32_t smem_u32(const void* p) {
    uint32_t a;
    asm("{ .reg .u64 t; cvta.to.shared.u64 t, %1; cvt.u32.u64 %0, t; }" : "=r"(a) : "l"(p));
    return a;
}
__device__ __forceinline__ void mma_bf16(float* c, const uint32_t* a, const uint32_t* b) {
    asm volatile(
        "mma.sync.aligned.m16n8k16.row.col.f32.bf16.bf16.f32 "
        "{%0,%1,%2,%3}, {%4,%5,%6,%7}, {%8,%9}, {%0,%1,%2,%3};"
        : "+f"(c[0]), "+f"(c[1]), "+f"(c[2]), "+f"(c[3])
        : "r"(a[0]), "r"(a[1]), "r"(a[2]), "r"(a[3]), "r"(b[0]), "r"(b[1]));
}
__device__ __forceinline__ void ldsm_x4(uint32_t* d, uint32_t addr) {
    asm volatile("ldmatrix.sync.aligned.m8n8.x4.shared.b16 {%0,%1,%2,%3}, [%4];"
                 : "=r"(d[0]), "=r"(d[1]), "=r"(d[2]), "=r"(d[3]) : "r"(addr));
}
__device__ __forceinline__ void ldsm_x4_t(uint32_t* d, uint32_t addr) {
    asm volatile("ldmatrix.sync.aligned.m8n8.x4.trans.shared.b16 {%0,%1,%2,%3}, [%4];"
                 : "=r"(d[0]), "=r"(d[1]), "=r"(d[2]), "=r"(d[3]) : "r"(addr));
}
__device__ __forceinline__ void ldsm_x2(uint32_t* d, uint32_t addr) {
    asm volatile("ldmatrix.sync.aligned.m8n8.x2.shared.b16 {%0,%1}, [%2];"
                 : "=r"(d[0]), "=r"(d[1]) : "r"(addr));
}
// hi = top-16-bit truncation of fp32 (exact in bf16, residual exact)
__device__ __forceinline__ uint32_t pack_hi(float x0, float x1) {
    uint32_t u0 = __float_as_uint(x0), u1 = __float_as_uint(x1);
    return (u0 >> 16) | (u1 & 0xFFFF0000u);
}
__device__ __forceinline__ uint32_t pack_lo(float x0, float x1) {
    float h0 = __uint_as_float(__float_as_uint(x0) & 0xFFFF0000u);
    float h1 = __uint_as_float(__float_as_uint(x1) & 0xFFFF0000u);
    __nv_bfloat162 v = __floats2bfloat162_rn(x0 - h0, x1 - h1);
    return *reinterpret_cast<uint32_t*>(&v);
}

// ================= bf16x3 HMMA GEMM (NT): C = A[M,K]*B[N,K]^T + bias =================
#define GBK 32
#define ROWH 40
#define TILE_H_BYTES (128 * ROWH * 2)
#define G_STAGE (4 * TILE_H_BYTES)
#define GEMM_SMEM (2 * G_STAGE)

__global__ void __launch_bounds__(256)
gemm_mma_k(const float* __restrict__ A, const float* __restrict__ Bm,
           const float* __restrict__ bias, float* __restrict__ Cm,
           int K, int ldc) {
    extern __shared__ char smem[];
    const uint32_t sb = smem_u32(smem);
    const int tid = threadIdx.x;
    const int wid = tid >> 5, lid = tid & 31;
    const int m0 = blockIdx.y * 128, n0 = blockIdx.x * 128;

    const int lr = tid >> 1;
    const int lc0 = (tid & 1) * 16;
    const float* Ap = A + (size_t)(m0 + lr) * K + lc0;
    const float* Bp = Bm + (size_t)(n0 + lr) * K + lc0;
    const uint32_t sts_off = (uint32_t)(lr * ROWH + lc0) * 2;

    const int wm = (wid >> 2) * 64, wn = (wid & 3) * 32;
    const int a_row = (lid & 7) + ((lid >> 3) & 1) * 8;
    const int a_kb  = ((lid >> 4) & 1) * 8;
    const int b_row = lid & 7;
    const int b_kb  = ((lid >> 3) & 1) * 8;

    float acc[4][4][4];
#pragma unroll
    for (int i = 0; i < 4; i++)
#pragma unroll
        for (int j = 0; j < 4; j++)
#pragma unroll
            for (int c = 0; c < 4; c++) acc[i][j][c] = 0.f;

    const int nch = K / GBK;
    float4 la[4], lb[4];

#pragma unroll
    for (int j = 0; j < 4; j++) { la[j] = *(const float4*)(Ap + j * 4); lb[j] = *(const float4*)(Bp + j * 4); }
#pragma unroll
    for (int j = 0; j < 4; j++) {
        uint32_t o = sts_off + j * 8;
        *(uint2*)(smem + 0 * TILE_H_BYTES + o) = make_uint2(pack_hi(la[j].x, la[j].y), pack_hi(la[j].z, la[j].w));
        *(uint2*)(smem + 1 * TILE_H_BYTES + o) = make_uint2(pack_lo(la[j].x, la[j].y), pack_lo(la[j].z, la[j].w));
        *(uint2*)(smem + 2 * TILE_H_BYTES + o) = make_uint2(pack_hi(lb[j].x, lb[j].y), pack_hi(lb[j].z, lb[j].w));
        *(uint2*)(smem + 3 * TILE_H_BYTES + o) = make_uint2(pack_lo(lb[j].x, lb[j].y), pack_lo(lb[j].z, lb[j].w));
    }

    for (int ch = 0; ch < nch; ch++) {
        __syncthreads();
        if (ch + 1 < nch) {
            const size_t ko = (size_t)(ch + 1) * GBK;
#pragma unroll
            for (int j = 0; j < 4; j++) { la[j] = *(const float4*)(Ap + ko + j * 4); lb[j] = *(const float4*)(Bp + ko + j * 4); }
        }
        const uint32_t st = sb + (uint32_t)(ch & 1) * G_STAGE;
#pragma unroll
        for (int ks = 0; ks < 2; ks++) {
            uint32_t ah[4][4], al[4][4], bh[4][2], bl[4][2];
#pragma unroll
            for (int mt = 0; mt < 4; mt++) {
                uint32_t ro = (uint32_t)((wm + mt * 16 + a_row) * ROWH + ks * 16 + a_kb) * 2;
                ldsm_x4(ah[mt], st + 0 * TILE_H_BYTES + ro);
                ldsm_x4(al[mt], st + 1 * TILE_H_BYTES + ro);
            }
#pragma unroll
            for (int nt = 0; nt < 4; nt++) {
                uint32_t ro = (uint32_t)((wn + nt * 8 + b_row) * ROWH + ks * 16 + b_kb) * 2;
                ldsm_x2(bh[nt], st + 2 * TILE_H_BYTES + ro);
                ldsm_x2(bl[nt], st + 3 * TILE_H_BYTES + ro);
            }
#pragma unroll
            for (int mt = 0; mt < 4; mt++)
#pragma unroll
                for (int nt = 0; nt < 4; nt++) {
                    mma_bf16(acc[mt][nt], ah[mt], bh[nt]);
                    mma_bf16(acc[mt][nt], ah[mt], bl[nt]);
                    mma_bf16(acc[mt][nt], al[mt], bh[nt]);
                }
        }
        if (ch + 1 < nch) {
            char* dst = smem + ((ch + 1) & 1) * G_STAGE;
#pragma unroll
            for (int j = 0; j < 4; j++) {
                uint32_t o = sts_off + j * 8;
                *(uint2*)(dst + 0 * TILE_H_BYTES + o) = make_uint2(pack_hi(la[j].x, la[j].y), pack_hi(la[j].z, la[j].w));
                *(uint2*)(dst + 1 * TILE_H_BYTES + o) = make_uint2(pack_lo(la[j].x, la[j].y), pack_lo(la[j].z, la[j].w));
                *(uint2*)(dst + 2 * TILE_H_BYTES + o) = make_uint2(pack_hi(lb[j].x, lb[j].y), pack_hi(lb[j].z, lb[j].w));
                *(uint2*)(dst + 3 * TILE_H_BYTES + o) = make_uint2(pack_lo(lb[j].x, lb[j].y), pack_lo(lb[j].z, lb[j].w));
            }
        }
    }

    const int cr = lid >> 2, cc = (lid & 3) * 2;
#pragma unroll
    for (int mt = 0; mt < 4; mt++) {
#pragma unroll
        for (int nt = 0; nt < 4; nt++) {
            int gr = m0 + wm + mt * 16 + cr;
            int gc = n0 + wn + nt * 8 + cc;
            float b0 = bias[gc], b1 = bias[gc + 1];
            float* p0 = Cm + (size_t)gr * ldc + gc;
            float* p1 = Cm + (size_t)(gr + 8) * ldc + gc;
            *(float2*)p0 = make_float2(acc[mt][nt][0] + b0, acc[mt][nt][1] + b1);
            *(float2*)p1 = make_float2(acc[mt][nt][2] + b0, acc[mt][nt][3] + b1);
        }
    }
}

// ================= HMMA flash attention (causal, fused RoPE, bf16x3) =================
// BQ=128, BK=64, 8 warps; warp w owns q rows [w*16, w*16+16).
// smem (halfs, rows padded to 136): Qh,Ql [128x128]; Kh,Kl,Vh,Vl [64x128].
#define FROWH 136
#define FQH 0
#define FQL 17408
#define FKH 34816
#define FKL 43520
#define FVH 52224
#define FVL 60928
#define FA2_SMEM (69632 * 2)

__global__ void __launch_bounds__(256, 1)
flash_attn_mma_k() {
    extern __shared__ uint16_t sh[];
    const uint32_t sb = smem_u32(sh);
    const int tid = threadIdx.x, wid = tid >> 5, lane = tid & 31;
    const int qb = blockIdx.x, h = blockIdx.y, b = blockIdx.z;
    const int q0 = qb * 128;
    const float scale = 0.08838834764831845f;  // 1/sqrt(128)

    // ---- Q tile load + RoPE + hi/lo split (2 threads per row)
    {
        const int r = tid >> 1, c0 = (tid & 1) * 32;
        const int t = q0 + r;
        const float* qp = g_qkv + (size_t)(b * T_ + t) * C3_ + h * HD_;
        const float* cp = g_cos + t * 64;
        const float* sp = g_sin + t * 64;
        const uint32_t so = (uint32_t)(r * FROWH);
#pragma unroll
        for (int j = 0; j < 8; j++) {
            int c = c0 + j * 4;
            float4 xa = *(const float4*)(qp + c);
            float4 xb = *(const float4*)(qp + c + 64);
            float4 cs = *(const float4*)(cp + c);
            float4 sn = *(const float4*)(sp + c);
            float4 ra, rb;
            ra.x = xa.x * cs.x - xb.x * sn.x;  rb.x = xb.x * cs.x + xa.x * sn.x;
            ra.y = xa.y * cs.y - xb.y * sn.y;  rb.y = xb.y * cs.y + xa.y * sn.y;
            ra.z = xa.z * cs.z - xb.z * sn.z;  rb.z = xb.z * cs.z + xa.z * sn.z;
            ra.w = xa.w * cs.w - xb.w * sn.w;  rb.w = xb.w * cs.w + xa.w * sn.w;
            *(uint2*)(sh + FQH + so + c)      = make_uint2(pack_hi(ra.x, ra.y), pack_hi(ra.z, ra.w));
            *(uint2*)(sh + FQL + so + c)      = make_uint2(pack_lo(ra.x, ra.y), pack_lo(ra.z, ra.w));
            *(uint2*)(sh + FQH + so + c + 64) = make_uint2(pack_hi(rb.x, rb.y), pack_hi(rb.z, rb.w));
            *(uint2*)(sh + FQL + so + c + 64) = make_uint2(pack_lo(rb.x, rb.y), pack_lo(rb.z, rb.w));
        }
    }

    float m_[2] = {-1e30f, -1e30f}, l_[2] = {0.f, 0.f};
    float o_[16][4];
#pragma unroll
    for (int nt = 0; nt < 16; nt++)
#pragma unroll
        for (int c = 0; c < 4; c++) o_[nt][c] = 0.f;

    const int ktmax = 2 * qb + 1;
    for (int kt = 0; kt <= ktmax; kt++) {
        // ---- K tile load + RoPE + split; V tile load + split (4 threads per row)
        {
            const int r = tid >> 2;
            const int t = kt * 64 + r;
            const float* kp = g_qkv + (size_t)(b * T_ + t) * C3_ + C_ + h * HD_;
            const float* cp = g_cos + t * 64;
            const float* sp = g_sin + t * 64;
            const uint32_t so = (uint32_t)(r * FROWH);
            const int c0 = (tid & 3) * 16;
#pragma unroll
            for (int j = 0; j < 4; j++) {
                int c = c0 + j * 4;
                float4 xa = *(const float4*)(kp + c);
                float4 xb = *(const float4*)(kp + c + 64);
                float4 cs = *(const float4*)(cp + c);
                float4 sn = *(const float4*)(sp + c);
                float4 ra, rb;
                ra.x = xa.x * cs.x - xb.x * sn.x;  rb.x = xb.x * cs.x + xa.x * sn.x;
                ra.y = xa.y * cs.y - xb.y * sn.y;  rb.y = xb.y * cs.y + xa.y * sn.y;
                ra.z = xa.z * cs.z - xb.z * sn.z;  rb.z = xb.z * cs.z + xa.z * sn.z;
                ra.w = xa.w * cs.w - xb.w * sn.w;  rb.w = xb.w * cs.w + xa.w * sn.w;
                *(uint2*)(sh + FKH + so + c)      = make_uint2(pack_hi(ra.x, ra.y), pack_hi(ra.z, ra.w));
                *(uint2*)(sh + FKL + so + c)      = make_uint2(pack_lo(ra.x, ra.y), pack_lo(ra.z, ra.w));
                *(uint2*)(sh + FKH + so + c + 64) = make_uint2(pack_hi(rb.x, rb.y), pack_hi(rb.z, rb.w));
                *(uint2*)(sh + FKL + so + c + 64) = make_uint2(pack_lo(rb.x, rb.y), pack_lo(rb.z, rb.w));
            }
            const float* vp = kp + C_;
            const int vc0 = (tid & 3) * 32;
#pragma unroll
            for (int j = 0; j < 8; j++) {
                int c = vc0 + j * 4;
                float4 v = *(const float4*)(vp + c);
                *(uint2*)(sh + FVH + so + c) = make_uint2(pack_hi(v.x, v.y), pack_hi(v.z, v.w));
                *(uint2*)(sh + FVL + so + c) = make_uint2(pack_lo(v.x, v.y), pack_lo(v.z, v.w));
            }
        }
        __syncthreads();

        // ---- S = Q K^T  (bf16x3), warp tile 16x64
        float s[8][4];
#pragma unroll
        for (int nt = 0; nt < 8; nt++)
#pragma unroll
            for (int c = 0; c < 4; c++) s[nt][c] = 0.f;

#pragma unroll
        for (int kk = 0; kk < 8; kk++) {
            uint32_t aqh[4], aql[4];
            const uint32_t ar = sb + (uint32_t)((wid * 16 + (lane & 15)) * FROWH + kk * 16 + (lane >> 4) * 8) * 2;
            ldsm_x4(aqh, ar + FQH * 2);
            ldsm_x4(aql, ar + FQL * 2);
#pragma unroll
            for (int np = 0; np < 4; np++) {
                uint32_t bh[4], bl[4];
                const uint32_t br = sb + (uint32_t)((np * 16 + (lane & 7) + ((lane >> 4) & 1) * 8) * FROWH +
                                                    kk * 16 + ((lane >> 3) & 1) * 8) * 2;
                ldsm_x4(bh, br + FKH * 2);
                ldsm_x4(bl, br + FKL * 2);
                mma_bf16(s[2 * np],     aqh, bh);
                mma_bf16(s[2 * np],     aqh, bl);
                mma_bf16(s[2 * np],     aql, bh);
                mma_bf16(s[2 * np + 1], aqh, bh + 2);
                mma_bf16(s[2 * np + 1], aqh, bl + 2);
                mma_bf16(s[2 * np + 1], aql, bh + 2);
            }
        }

        // ---- online softmax (rows owned by 4-lane groups)
        const bool msk = (kt >= 2 * qb);
        const int rbase = q0 + wid * 16 + (lane >> 2);
        const int kbase = kt * 64 + (lane & 3) * 2;
#pragma unroll
        for (int i = 0; i < 2; i++) {
            const int rg = rbase + i * 8;
            float mx = -1e30f;
#pragma unroll
            for (int nt = 0; nt < 8; nt++)
#pragma unroll
                for (int c = 0; c < 2; c++) {
                    float v = s[nt][i * 2 + c] * scale;
                    if (msk && (kbase + nt * 8 + c) > rg) v = -1e30f;
                    s[nt][i * 2 + c] = v;
                    mx = fmaxf(mx, v);
                }
            mx = fmaxf(mx, __shfl_xor_sync(0xffffffffu, mx, 1));
            mx = fmaxf(mx, __shfl_xor_sync(0xffffffffu, mx, 2));
            float mn = fmaxf(m_[i], mx);
            float al = __expf(m_[i] - mn);
            m_[i] = mn;
            float rs = 0.f;
#pragma unroll
            for (int nt = 0; nt < 8; nt++)
#pragma unroll
                for (int c = 0; c < 2; c++) {
                    float p = __expf(s[nt][i * 2 + c] - mn);
                    s[nt][i * 2 + c] = p;
                    rs += p;
                }
            rs += __shfl_xor_sync(0xffffffffu, rs, 1);
            rs += __shfl_xor_sync(0xffffffffu, rs, 2);
            l_[i] = l_[i] * al + rs;
#pragma unroll
            for (int nt = 0; nt < 16; nt++) { o_[nt][i * 2] *= al; o_[nt][i * 2 + 1] *= al; }
        }

        // ---- O += P V  (bf16x3; P fragments built in-register from S)
#pragma unroll
        for (int kk = 0; kk < 4; kk++) {
            uint32_t ph[4], pl[4];
            ph[0] = pack_hi(s[2 * kk][0], s[2 * kk][1]);
            ph[1] = pack_hi(s[2 * kk][2], s[2 * kk][3]);
            ph[2] = pack_hi(s[2 * kk + 1][0], s[2 * kk + 1][1]);
            ph[3] = pack_hi(s[2 * kk + 1][2], s[2 * kk + 1][3]);
            pl[0] = pack_lo(s[2 * kk][0], s[2 * kk][1]);
            pl[1] = pack_lo(s[2 * kk][2], s[2 * kk][3]);
            pl[2] = pack_lo(s[2 * kk + 1][0], s[2 * kk + 1][1]);
            pl[3] = pack_lo(s[2 * kk + 1][2], s[2 * kk + 1][3]);
#pragma unroll
            for (int np = 0; np < 8; np++) {
                uint32_t vh[4], vl[4];
                const uint32_t vr = sb + (uint32_t)((kk * 16 + (lane & 7) + ((lane >> 3) & 1) * 8) * FROWH +
                                                    np * 16 + ((lane >> 4) & 1) * 8) * 2;
                ldsm_x4_t(vh, vr + FVH * 2);
                ldsm_x4_t(vl, vr + FVL * 2);
                mma_bf16(o_[2 * np],     ph, vh);
                mma_bf16(o_[2 * np],     ph, vl);
                mma_bf16(o_[2 * np],     pl, vh);
                mma_bf16(o_[2 * np + 1], ph, vh + 2);
                mma_bf16(o_[2 * np + 1], ph, vl + 2);
                mma_bf16(o_[2 * np + 1], pl, vh + 2);
            }
        }
        __syncthreads();
    }

    // ---- normalize + store to g_att [B,T,C]
    const float inv0 = 1.f / l_[0], inv1 = 1.f / l_[1];
    const int rg0 = q0 + wid * 16 + (lane >> 2);
    float* ob = g_att + (size_t)(b * T_) * C_ + h * HD_ + (lane & 3) * 2;
#pragma unroll
    for (int nt = 0; nt < 16; nt++) {
        *(float2*)(ob + (size_t)rg0 * C_ + nt * 8)       = make_float2(o_[nt][0] * inv0, o_[nt][1] * inv0);
        *(float2*)(ob + (size_t)(rg0 + 8) * C_ + nt * 8) = make_float2(o_[nt][2] * inv1, o_[nt][3] * inv1);
    }
}

// ---------------- launch ----------------
extern "C" void kernel_launch(void* const* d_in, const int* in_sizes, int n_in,
                              void* d_out, int out_size) {
    const float* x    = (const float*)d_in[0];
    const float* Wqkv = (const float*)d_in[1];
    const float* bqkv = (const float*)d_in[2];
    const float* Wo   = (const float*)d_in[3];
    const float* bo   = (const float*)d_in[4];
    float* out = (float*)d_out;

    void* qkv_p = nullptr; cudaGetSymbolAddress(&qkv_p, g_qkv);
    void* att_p = nullptr; cudaGetSymbolAddress(&att_p, g_att);

    cudaFuncSetAttribute(gemm_mma_k, cudaFuncAttributeMaxDynamicSharedMemorySize, GEMM_SMEM);
    cudaFuncSetAttribute(flash_attn_mma_k, cudaFuncAttributeMaxDynamicSharedMemorySize, FA2_SMEM);

    // 1. RoPE tables
    rope_tables_k<<<(T_ * 64 + 255) / 256, 256>>>();
    // 2. QKV projection (HMMA bf16x3)
    gemm_mma_k<<<dim3(C3_ / 128, M_ / 128), 256, GEMM_SMEM>>>(x, Wqkv, bqkv, (float*)qkv_p, C_, C3_);
    // 3. causal flash attention (HMMA, fused RoPE) -> g_att [B,T,C]
    flash_attn_mma_k<<<dim3(T_ / 128, H_, B_), 256, FA2_SMEM>>>();
    // 4. output projection (HMMA bf16x3) -> d_out
    gemm_mma_k<<<dim3(C_ / 128, M_ / 128), 256, GEMM_SMEM>>>((const float*)att_p, Wo, bo, out, C_, C_);
}